// round 8
// baseline (speedup 1.0000x reference)
#include <cuda_runtime.h>

// ButterflyLinear: 12 butterfly stages on N=4096, TOKENS=8192.
// Stage 0 pairs (j, j^1); stages 1..11 all pair (j, j^2) => transform is
// block-diagonal in 4-element groups. Kernel 1 folds per-group 4x4s
// (column-parallel). Kernel 2 streams out = blockdiag(A)*x + bias.
// R8 change: apply uses batch-of-2 + launch_bounds(256,6) to fit 40 regs ->
// 6 CTAs/SM (48 warps) for more memory-level parallelism.

#define TOKENS 8192
#define NCOLS  4096
#define DEPTH  12
#define GROUPS (NCOLS / 4)   // 1024
#define PAIRS  (NCOLS / 2)   // 2048 factor pairs per stage
#define T_PER  8             // tokens per thread -> 4096 blocks

// Scratch: 1024 groups x 4 columns (each column = float4) = 64 KB.
// g_C[g*4+e] = (A[0][e], A[1][e], A[2][e], A[3][e])
__device__ float4 g_C[GROUPS * 4];

// ---------------------------------------------------------------------------
// Kernel 1: one thread per (group, column); column-separable fold with
// front-batched MLP=24 loads (one DRAM round-trip). 64 blocks -> 64 SMs.
// factors layout: F[stage][pair][c][d] as float4 per pair:
//   f.x=f[0][0], f.y=f[0][1], f.z=f[1][0], f.w=f[1][1]
// Stage semantics: y[d] = sum_c pair_in[c] * f[c][d]
// ---------------------------------------------------------------------------
__global__ void butterfly_precompute(const float4* __restrict__ F4) {
    int t = blockIdx.x * blockDim.x + threadIdx.x;   // 0..4095
    int g = t >> 2;
    int e = t & 3;
    int j0 = 4 * g;

    float4 fa[DEPTH], fb[DEPTH];
    fa[0] = F4[2 * g];
    fb[0] = F4[2 * g + 1];
    #pragma unroll
    for (int s = 1; s < DEPTH; s++) {
        int block = 1 << (s + 1);
        int pA = ((j0 >> (s + 1)) << s) | ((j0 & (block - 1)) >> 2);
        int pB = pA + (1 << (s - 1));
        fa[s] = F4[s * PAIRS + pA];
        fb[s] = F4[s * PAIRS + pB];
    }

    float A0, A1, A2, A3;
    {
        float4 f0 = fa[0], f1 = fb[0];
        bool lo = (e < 2);
        float4 f = lo ? f0 : f1;
        float u = (e & 1) ? f.z : f.x;
        float v = (e & 1) ? f.w : f.y;
        A0 = lo ? u : 0.f;
        A1 = lo ? v : 0.f;
        A2 = lo ? 0.f : u;
        A3 = lo ? 0.f : v;
    }

    #pragma unroll
    for (int s = 1; s < DEPTH; s++) {
        float a00 = fa[s].x, a01 = fa[s].y, a10 = fa[s].z, a11 = fa[s].w;
        float b00 = fb[s].x, b01 = fb[s].y, b10 = fb[s].z, b11 = fb[s].w;
        float r0 = A0, r1 = A1, r2 = A2, r3 = A3;
        A0 = a00 * r0 + a10 * r2;
        A2 = a01 * r0 + a11 * r2;
        A1 = b00 * r1 + b10 * r3;
        A3 = b01 * r1 + b11 * r3;
    }

    g_C[t] = make_float4(A0, A1, A2, A3);
}

// ---------------------------------------------------------------------------
// Kernel 2: out[t, group g] = A_g * x[t, g] + bias_g (column-major A):
//   r = b + v.x*c0 + v.y*c1 + v.z*c2 + v.w*c3
// Batch-of-2 body, 40-reg budget, 6 CTAs/SM.
// ---------------------------------------------------------------------------
__global__ void __launch_bounds__(256, 6)
butterfly_apply(const float4* __restrict__ x,
                const float4* __restrict__ bias4,
                float4* __restrict__ out) {
    int g  = blockIdx.x * blockDim.x + threadIdx.x;  // 0..GROUPS-1
    int t0 = blockIdx.y * T_PER;

    float4 c0 = g_C[g * 4 + 0];
    float4 c1 = g_C[g * 4 + 1];
    float4 c2 = g_C[g * 4 + 2];
    float4 c3 = g_C[g * 4 + 3];
    float4 b  = bias4[g];

    const float4* xp = x   + (size_t)t0 * GROUPS + g;
    float4*       op = out + (size_t)t0 * GROUPS + g;

    #pragma unroll
    for (int ii = 0; ii < T_PER; ii += 2) {
        float4 v0 = __ldcs(xp + (size_t)(ii + 0) * GROUPS);
        float4 v1 = __ldcs(xp + (size_t)(ii + 1) * GROUPS);

        float4 r0, r1;
        r0.x = b.x + v0.x*c0.x + v0.y*c1.x + v0.z*c2.x + v0.w*c3.x;
        r0.y = b.y + v0.x*c0.y + v0.y*c1.y + v0.z*c2.y + v0.w*c3.y;
        r0.z = b.z + v0.x*c0.z + v0.y*c1.z + v0.z*c2.z + v0.w*c3.z;
        r0.w = b.w + v0.x*c0.w + v0.y*c1.w + v0.z*c2.w + v0.w*c3.w;

        r1.x = b.x + v1.x*c0.x + v1.y*c1.x + v1.z*c2.x + v1.w*c3.x;
        r1.y = b.y + v1.x*c0.y + v1.y*c1.y + v1.z*c2.y + v1.w*c3.y;
        r1.z = b.z + v1.x*c0.z + v1.y*c1.z + v1.z*c2.z + v1.w*c3.z;
        r1.w = b.w + v1.x*c0.w + v1.y*c1.w + v1.z*c2.w + v1.w*c3.w;

        __stcs(op + (size_t)(ii + 0) * GROUPS, r0);
        __stcs(op + (size_t)(ii + 1) * GROUPS, r1);
    }
}

// ---------------------------------------------------------------------------
extern "C" void kernel_launch(void* const* d_in, const int* in_sizes, int n_in,
                              void* d_out, int out_size) {
    const float* x = nullptr;
    const float* factors = nullptr;
    const float* bias = nullptr;
    for (int i = 0; i < n_in; i++) {
        if (in_sizes[i] == TOKENS * NCOLS)            x = (const float*)d_in[i];
        else if (in_sizes[i] == DEPTH * PAIRS * 4)    factors = (const float*)d_in[i];
        else if (in_sizes[i] == NCOLS)                bias = (const float*)d_in[i];
    }

    // Kernel 1: 4096 threads = 1 per (group, column), spread over 64 SMs.
    butterfly_precompute<<<64, 64>>>((const float4*)factors);

    // Kernel 2: (4, 1024) = 4096 blocks, 8 tokens per thread.
    dim3 grid(GROUPS / 256, TOKENS / T_PER);
    butterfly_apply<<<grid, 256>>>((const float4*)x,
                                   (const float4*)bias,
                                   (float4*)d_out);
}